// round 3
// baseline (speedup 1.0000x reference)
#include <cuda_runtime.h>
#include <cstdint>
#include <cstddef>

// Problem constants
#define T_DIM 1024
#define M_DIM 128
#define A_DIM 64
#define D_DIM 128

// Shared-memory strides (in floats), chosen for bank-conflict-free fragment loads:
//  A-side arrays (rows indexed by g across lanes): stride % 32 == 12 -> distinct banks
//  B-side arrays (rows indexed by q across lanes): stride % 32 == 8  -> distinct banks
#define LDX   76    // Xs:    128 x 64  (A operand of GEMM1)
#define LDB   136   // W1s / W2s / Ss   (B operands)
#define LDA2  140   // Hs / Mains       (A operands of GEMM2/3)

// SMEM layout (float offsets). Unions:
//   region1 [0,18432): Xs(9728) + W1s(8704)  UNION  W2s(17408)
//   region2 [18432,36352): Hs(17920) UNION Mains(17920)
//   region3 [36352,53760): Ss(17408)
//   biases  [53760,54016)
#define OFF_X    0
#define OFF_W1   9728
#define OFF_W2   0
#define OFF_H    18432
#define OFF_MAIN 18432
#define OFF_S    36352
#define OFF_B1   53760
#define OFF_B2   53888
#define SMEM_FLOATS 54016
#define SMEM_BYTES  (SMEM_FLOATS * 4)   // 216064 bytes

__device__ __forceinline__ unsigned f2tf32(float x) {
    unsigned u;
    asm("cvt.rna.tf32.f32 %0, %1;" : "=r"(u) : "f"(x));
    return u;
}

__device__ __forceinline__ void mma_tf32(float c[4],
                                         unsigned a0, unsigned a1, unsigned a2, unsigned a3,
                                         unsigned b0, unsigned b1) {
    asm volatile(
        "mma.sync.aligned.m16n8k8.row.col.f32.tf32.tf32.f32 "
        "{%0,%1,%2,%3}, {%4,%5,%6,%7}, {%8,%9}, {%0,%1,%2,%3};"
        : "+f"(c[0]), "+f"(c[1]), "+f"(c[2]), "+f"(c[3])
        : "r"(a0), "r"(a1), "r"(a2), "r"(a3), "r"(b0), "r"(b1));
}

// Warp-level 16x128 tile GEMM from SMEM operands (tf32 bit patterns already in place).
// A: rows rowA0..rowA0+15, stride lda. B: K x 128, stride ldb. ksteps * 8 = K.
__device__ __forceinline__ void gemm_tile(const float* __restrict__ sm,
                                          int offA, int lda, int offB, int ldb,
                                          int rowA0, int ksteps,
                                          int g, int q, float acc[16][4]) {
    const float* Ap = sm + offA;
    const float* Bp = sm + offB;
    #pragma unroll 4
    for (int ks = 0; ks < ksteps; ks++) {
        const int k0 = ks * 8;
        unsigned a0 = __float_as_uint(Ap[(rowA0 + g    ) * lda + k0 + q    ]);
        unsigned a1 = __float_as_uint(Ap[(rowA0 + g + 8) * lda + k0 + q    ]);
        unsigned a2 = __float_as_uint(Ap[(rowA0 + g    ) * lda + k0 + q + 4]);
        unsigned a3 = __float_as_uint(Ap[(rowA0 + g + 8) * lda + k0 + q + 4]);
        #pragma unroll
        for (int nt = 0; nt < 16; nt++) {
            unsigned b0 = __float_as_uint(Bp[(k0 + q    ) * ldb + nt * 8 + g]);
            unsigned b1 = __float_as_uint(Bp[(k0 + q + 4) * ldb + nt * 8 + g]);
            mma_tf32(acc[nt], a0, a1, a2, a3, b0, b1);
        }
    }
}

__device__ __forceinline__ void zero_acc(float acc[16][4]) {
    #pragma unroll
    for (int nt = 0; nt < 16; nt++)
        #pragma unroll
        for (int r = 0; r < 4; r++) acc[nt][r] = 0.0f;
}

__global__ __launch_bounds__(256, 1)
void slam_fused_kernel(const float* __restrict__ x_main_last,  // already offset to last batch
                       const float* __restrict__ x_aux,
                       const float* __restrict__ W1,
                       const float* __restrict__ b1,
                       const float* __restrict__ W2,
                       const float* __restrict__ b2,
                       float* __restrict__ out) {
    extern __shared__ float sm[];
    const int t    = blockIdx.x;
    const int tid  = threadIdx.x;
    const int warp = tid >> 5;
    const int lane = tid & 31;
    const int g    = lane >> 2;  // 0..7
    const int q    = lane & 3;   // 0..3
    const int r0   = warp * 16;  // this warp's output-row base

    // ---------------- Phase 0: stage X_t, W1, biases ----------------
    // Xs[m][a] = tf32(x_aux[m, t, a])
    for (int idx = tid; idx < M_DIM * A_DIM; idx += 256) {
        const int m = idx >> 6, a = idx & 63;
        const float v = x_aux[(size_t)m * (T_DIM * A_DIM) + (size_t)t * A_DIM + a];
        sm[OFF_X + m * LDX + a] = __uint_as_float(f2tf32(v));
    }
    // W1s[k][n]
    for (int idx = tid; idx < A_DIM * D_DIM; idx += 256) {
        const int k = idx >> 7, n = idx & 127;
        sm[OFF_W1 + k * LDB + n] = __uint_as_float(f2tf32(W1[idx]));
    }
    if (tid < 128) {
        sm[OFF_B1 + tid] = b1[tid];
        sm[OFF_B2 + tid] = b2[tid];
    }
    __syncthreads();

    float acc[16][4];

    // ---------------- Phase 1: H = relu(X @ W1 + b1) ----------------
    zero_acc(acc);
    gemm_tile(sm, OFF_X, LDX, OFF_W1, LDB, r0, A_DIM / 8, g, q, acc);
    // epilogue -> Hs (tf32)
    #pragma unroll
    for (int nt = 0; nt < 16; nt++) {
        const int c0 = nt * 8 + 2 * q;
        const float bb0 = sm[OFF_B1 + c0];
        const float bb1 = sm[OFF_B1 + c0 + 1];
        const float v00 = fmaxf(acc[nt][0] + bb0, 0.0f);
        const float v01 = fmaxf(acc[nt][1] + bb1, 0.0f);
        const float v10 = fmaxf(acc[nt][2] + bb0, 0.0f);
        const float v11 = fmaxf(acc[nt][3] + bb1, 0.0f);
        sm[OFF_H + (r0 + g    ) * LDA2 + c0    ] = __uint_as_float(f2tf32(v00));
        sm[OFF_H + (r0 + g    ) * LDA2 + c0 + 1] = __uint_as_float(f2tf32(v01));
        sm[OFF_H + (r0 + g + 8) * LDA2 + c0    ] = __uint_as_float(f2tf32(v10));
        sm[OFF_H + (r0 + g + 8) * LDA2 + c0 + 1] = __uint_as_float(f2tf32(v11));
    }
    __syncthreads();   // Xs/W1s reads + Hs writes complete

    // ---------------- Phase 2: load W2 (overwrites Xs/W1s region) ----------------
    for (int idx = tid; idx < D_DIM * M_DIM; idx += 256) {
        const int k = idx >> 7, n = idx & 127;
        sm[OFF_W2 + k * LDB + n] = __uint_as_float(f2tf32(W2[idx]));
    }
    __syncthreads();

    // ---------------- Phase 3: S = H @ W2 + b2 ----------------
    zero_acc(acc);
    gemm_tile(sm, OFF_H, LDA2, OFF_W2, LDB, r0, D_DIM / 8, g, q, acc);
    #pragma unroll
    for (int nt = 0; nt < 16; nt++) {
        const int c0 = nt * 8 + 2 * q;
        const float bb0 = sm[OFF_B2 + c0];
        const float bb1 = sm[OFF_B2 + c0 + 1];
        sm[OFF_S + (r0 + g    ) * LDB + c0    ] = __uint_as_float(f2tf32(acc[nt][0] + bb0));
        sm[OFF_S + (r0 + g    ) * LDB + c0 + 1] = __uint_as_float(f2tf32(acc[nt][1] + bb1));
        sm[OFF_S + (r0 + g + 8) * LDB + c0    ] = __uint_as_float(f2tf32(acc[nt][2] + bb0));
        sm[OFF_S + (r0 + g + 8) * LDB + c0 + 1] = __uint_as_float(f2tf32(acc[nt][3] + bb1));
    }
    __syncthreads();   // Hs reads + Ss writes complete

    // ---------------- Phase 4: load Main_t (overwrites Hs region) ----------------
    {
        const float* mp = x_main_last + (size_t)t * (M_DIM * M_DIM);
        for (int idx = tid; idx < M_DIM * M_DIM; idx += 256) {
            const int i = idx >> 7, j = idx & 127;
            sm[OFF_MAIN + i * LDA2 + j] = __uint_as_float(f2tf32(mp[idx]));
        }
    }
    __syncthreads();

    // ---------------- Phase 5: out_t = Main_t @ S_t ----------------
    zero_acc(acc);
    gemm_tile(sm, OFF_MAIN, LDA2, OFF_S, LDB, r0, M_DIM / 8, g, q, acc);

    // epilogue -> global (float2 stores, 8B aligned)
    float* op = out + (size_t)t * (M_DIM * M_DIM);
    #pragma unroll
    for (int nt = 0; nt < 16; nt++) {
        const int c0 = nt * 8 + 2 * q;
        float2 v0 = make_float2(acc[nt][0], acc[nt][1]);
        float2 v1 = make_float2(acc[nt][2], acc[nt][3]);
        *reinterpret_cast<float2*>(op + (size_t)(r0 + g    ) * M_DIM + c0) = v0;
        *reinterpret_cast<float2*>(op + (size_t)(r0 + g + 8) * M_DIM + c0) = v1;
    }
}

extern "C" void kernel_launch(void* const* d_in, const int* in_sizes, int n_in,
                              void* d_out, int out_size) {
    const float* x_main = (const float*)d_in[0];
    const float* x_aux  = (const float*)d_in[1];
    const float* W1     = (const float*)d_in[2];
    const float* b1     = (const float*)d_in[3];
    const float* W2     = (const float*)d_in[4];
    const float* b2     = (const float*)d_in[5];
    float* out = (float*)d_out;

    // last batch index of x_main: x_main[N-1, :, 0, :, :]
    const size_t slice = (size_t)T_DIM * M_DIM * M_DIM;            // 16,777,216
    const size_t main_off = (size_t)in_sizes[0] - slice;           // (N-1)*T*M*M
    const float* x_main_last = x_main + main_off;

    // Allow >48KB dynamic smem (idempotent; host-side attr set, graph-capture safe)
    cudaFuncSetAttribute(slam_fused_kernel,
                         cudaFuncAttributeMaxDynamicSharedMemorySize, SMEM_BYTES);

    slam_fused_kernel<<<T_DIM, 256, SMEM_BYTES>>>(x_main_last, x_aux, W1, b1, W2, b2, out);
}

// round 4
// speedup vs baseline: 1.0320x; 1.0320x over previous
#include <cuda_runtime.h>
#include <cstdint>
#include <cstddef>

// Problem constants
#define T_DIM 1024
#define M_DIM 128
#define A_DIM 64
#define D_DIM 128

// Shared-memory strides (in floats), chosen for bank-conflict-free fragment loads:
//  A-side arrays (rows indexed by g across lanes): stride % 32 == 12 -> distinct banks
//  B-side arrays (rows indexed by q across lanes): stride % 32 == 8  -> distinct banks
#define LDX   76    // Xs:    128 x 64  (A operand of GEMM1)
#define LDB   136   // W1s / W2s / Ss   (B operands)
#define LDA2  140   // Hs / Mains       (A operands of GEMM2/3)

// SMEM layout (float offsets). Unions:
//   region1 [0,18432): Xs(9728) + W1s(8704)  UNION  W2s(17408)
//   region2 [18432,36352): Hs(17920) UNION Mains(17920)
//   region3 [36352,53760): Ss(17408)
//   biases  [53760,54016)
#define OFF_X    0
#define OFF_W1   9728
#define OFF_W2   0
#define OFF_H    18432
#define OFF_MAIN 18432
#define OFF_S    36352
#define OFF_B1   53760
#define OFF_B2   53888
#define SMEM_FLOATS 54016
#define SMEM_BYTES  (SMEM_FLOATS * 4)   // 216064 bytes

#define NTHREADS 512

__device__ __forceinline__ unsigned f2tf32(float x) {
    unsigned u;
    asm("cvt.rna.tf32.f32 %0, %1;" : "=r"(u) : "f"(x));
    return u;
}

__device__ __forceinline__ void mma_tf32(float c[4],
                                         unsigned a0, unsigned a1, unsigned a2, unsigned a3,
                                         unsigned b0, unsigned b1) {
    asm volatile(
        "mma.sync.aligned.m16n8k8.row.col.f32.tf32.tf32.f32 "
        "{%0,%1,%2,%3}, {%4,%5,%6,%7}, {%8,%9}, {%0,%1,%2,%3};"
        : "+f"(c[0]), "+f"(c[1]), "+f"(c[2]), "+f"(c[3])
        : "r"(a0), "r"(a1), "r"(a2), "r"(a3), "r"(b0), "r"(b1));
}

// Warp-level 16x64 tile GEMM from SMEM operands (tf32 bit patterns already in place).
// A: rows rowA0..rowA0+15, stride lda. B: K x 128, stride ldb; this warp covers
// columns [nbase*8, nbase*8+64). ksteps * 8 = K.
__device__ __forceinline__ void gemm_tile(const float* __restrict__ sm,
                                          int offA, int lda, int offB, int ldb,
                                          int rowA0, int nbase, int ksteps,
                                          int g, int q, float acc[8][4]) {
    const float* Ap = sm + offA;
    const float* Bp = sm + offB;
    #pragma unroll 4
    for (int ks = 0; ks < ksteps; ks++) {
        const int k0 = ks * 8;
        unsigned a0 = __float_as_uint(Ap[(rowA0 + g    ) * lda + k0 + q    ]);
        unsigned a1 = __float_as_uint(Ap[(rowA0 + g + 8) * lda + k0 + q    ]);
        unsigned a2 = __float_as_uint(Ap[(rowA0 + g    ) * lda + k0 + q + 4]);
        unsigned a3 = __float_as_uint(Ap[(rowA0 + g + 8) * lda + k0 + q + 4]);
        #pragma unroll
        for (int nt = 0; nt < 8; nt++) {
            const int col = (nbase + nt) * 8 + g;
            unsigned b0 = __float_as_uint(Bp[(k0 + q    ) * ldb + col]);
            unsigned b1 = __float_as_uint(Bp[(k0 + q + 4) * ldb + col]);
            mma_tf32(acc[nt], a0, a1, a2, a3, b0, b1);
        }
    }
}

__device__ __forceinline__ void zero_acc(float acc[8][4]) {
    #pragma unroll
    for (int nt = 0; nt < 8; nt++)
        #pragma unroll
        for (int r = 0; r < 4; r++) acc[nt][r] = 0.0f;
}

__global__ __launch_bounds__(NTHREADS, 1)
void slam_fused_kernel(const float* __restrict__ x_main_last,  // already offset to last batch
                       const float* __restrict__ x_aux,
                       const float* __restrict__ W1,
                       const float* __restrict__ b1,
                       const float* __restrict__ W2,
                       const float* __restrict__ b2,
                       float* __restrict__ out) {
    extern __shared__ float sm[];
    const int t    = blockIdx.x;
    const int tid  = threadIdx.x;
    const int warp = tid >> 5;
    const int lane = tid & 31;
    const int g    = lane >> 2;       // 0..7
    const int q    = lane & 3;        // 0..3
    const int r0   = (warp >> 1) * 16;    // row-group base (8 groups of 16 rows)
    const int nbase = (warp & 1) * 8;     // nt half: tiles [nbase, nbase+8)

    // ---------------- Phase 0: stage X_t, W1, biases ----------------
    for (int idx = tid; idx < M_DIM * A_DIM; idx += NTHREADS) {
        const int m = idx >> 6, a = idx & 63;
        const float v = x_aux[(size_t)m * (T_DIM * A_DIM) + (size_t)t * A_DIM + a];
        sm[OFF_X + m * LDX + a] = __uint_as_float(f2tf32(v));
    }
    for (int idx = tid; idx < A_DIM * D_DIM; idx += NTHREADS) {
        const int k = idx >> 7, n = idx & 127;
        sm[OFF_W1 + k * LDB + n] = __uint_as_float(f2tf32(W1[idx]));
    }
    if (tid < 128) {
        sm[OFF_B1 + tid] = b1[tid];
        sm[OFF_B2 + tid] = b2[tid];
    }
    __syncthreads();

    float acc[8][4];

    // ---------------- Phase 1: H = relu(X @ W1 + b1) ----------------
    zero_acc(acc);
    gemm_tile(sm, OFF_X, LDX, OFF_W1, LDB, r0, nbase, A_DIM / 8, g, q, acc);
    #pragma unroll
    for (int nt = 0; nt < 8; nt++) {
        const int c0 = (nbase + nt) * 8 + 2 * q;
        const float bb0 = sm[OFF_B1 + c0];
        const float bb1 = sm[OFF_B1 + c0 + 1];
        float2 v0, v1;
        v0.x = __uint_as_float(f2tf32(fmaxf(acc[nt][0] + bb0, 0.0f)));
        v0.y = __uint_as_float(f2tf32(fmaxf(acc[nt][1] + bb1, 0.0f)));
        v1.x = __uint_as_float(f2tf32(fmaxf(acc[nt][2] + bb0, 0.0f)));
        v1.y = __uint_as_float(f2tf32(fmaxf(acc[nt][3] + bb1, 0.0f)));
        *reinterpret_cast<float2*>(&sm[OFF_H + (r0 + g    ) * LDA2 + c0]) = v0;
        *reinterpret_cast<float2*>(&sm[OFF_H + (r0 + g + 8) * LDA2 + c0]) = v1;
    }
    __syncthreads();   // Xs/W1s reads + Hs writes complete

    // ---------------- Phase 2: load W2 (overwrites Xs/W1s region) ----------------
    for (int idx = tid; idx < D_DIM * M_DIM; idx += NTHREADS) {
        const int k = idx >> 7, n = idx & 127;
        sm[OFF_W2 + k * LDB + n] = __uint_as_float(f2tf32(W2[idx]));
    }
    __syncthreads();

    // ---------------- Phase 3: S = H @ W2 + b2 ----------------
    zero_acc(acc);
    gemm_tile(sm, OFF_H, LDA2, OFF_W2, LDB, r0, nbase, D_DIM / 8, g, q, acc);
    #pragma unroll
    for (int nt = 0; nt < 8; nt++) {
        const int c0 = (nbase + nt) * 8 + 2 * q;
        const float bb0 = sm[OFF_B2 + c0];
        const float bb1 = sm[OFF_B2 + c0 + 1];
        float2 v0, v1;
        v0.x = __uint_as_float(f2tf32(acc[nt][0] + bb0));
        v0.y = __uint_as_float(f2tf32(acc[nt][1] + bb1));
        v1.x = __uint_as_float(f2tf32(acc[nt][2] + bb0));
        v1.y = __uint_as_float(f2tf32(acc[nt][3] + bb1));
        *reinterpret_cast<float2*>(&sm[OFF_S + (r0 + g    ) * LDB + c0]) = v0;
        *reinterpret_cast<float2*>(&sm[OFF_S + (r0 + g + 8) * LDB + c0]) = v1;
    }
    __syncthreads();   // Hs reads + Ss writes complete

    // ---------------- Phase 4: load Main_t (overwrites Hs region) ----------------
    {
        const float* mp = x_main_last + (size_t)t * (M_DIM * M_DIM);
        for (int idx = tid; idx < M_DIM * M_DIM; idx += NTHREADS) {
            const int i = idx >> 7, j = idx & 127;
            sm[OFF_MAIN + i * LDA2 + j] = __uint_as_float(f2tf32(mp[idx]));
        }
    }
    __syncthreads();

    // ---------------- Phase 5: out_t = Main_t @ S_t ----------------
    zero_acc(acc);
    gemm_tile(sm, OFF_MAIN, LDA2, OFF_S, LDB, r0, nbase, M_DIM / 8, g, q, acc);

    // epilogue -> global (float2 stores, 8B aligned)
    float* op = out + (size_t)t * (M_DIM * M_DIM);
    #pragma unroll
    for (int nt = 0; nt < 8; nt++) {
        const int c0 = (nbase + nt) * 8 + 2 * q;
        float2 v0 = make_float2(acc[nt][0], acc[nt][1]);
        float2 v1 = make_float2(acc[nt][2], acc[nt][3]);
        *reinterpret_cast<float2*>(op + (size_t)(r0 + g    ) * M_DIM + c0) = v0;
        *reinterpret_cast<float2*>(op + (size_t)(r0 + g + 8) * M_DIM + c0) = v1;
    }
}

extern "C" void kernel_launch(void* const* d_in, const int* in_sizes, int n_in,
                              void* d_out, int out_size) {
    const float* x_main = (const float*)d_in[0];
    const float* x_aux  = (const float*)d_in[1];
    const float* W1     = (const float*)d_in[2];
    const float* b1     = (const float*)d_in[3];
    const float* W2     = (const float*)d_in[4];
    const float* b2     = (const float*)d_in[5];
    float* out = (float*)d_out;

    // last batch index of x_main: x_main[N-1, :, 0, :, :]
    const size_t slice = (size_t)T_DIM * M_DIM * M_DIM;            // 16,777,216
    const size_t main_off = (size_t)in_sizes[0] - slice;           // (N-1)*T*M*M
    const float* x_main_last = x_main + main_off;

    cudaFuncSetAttribute(slam_fused_kernel,
                         cudaFuncAttributeMaxDynamicSharedMemorySize, SMEM_BYTES);

    slam_fused_kernel<<<T_DIM, NTHREADS, SMEM_BYTES>>>(x_main_last, x_aux, W1, b1, W2, b2, out);
}

// round 8
// speedup vs baseline: 1.9067x; 1.8476x over previous
#include <cuda_runtime.h>
#include <cstdint>
#include <cstddef>

// Problem constants
#define T_DIM 1024
#define M_DIM 128
#define A_DIM 64
#define D_DIM 128
#define NTHREADS 512

// ---------------- packed weight scratch (global, filled by setup kernel) -------------
// B-operand packed layout: entry (nt, ksp, slot) holds float4
//   e0 = B[16*ksp + q    ][8*nt + g]
//   e1 = B[16*ksp + q + 4][8*nt + g]
//   e2 = B[16*ksp + q + 8][8*nt + g]
//   e3 = B[16*ksp + q +12][8*nt + g]
// for consumer lane (g,q) stored at slot = g*4 + ((q + (g>>1)) & 3).
__device__ float g_W1p[16 * 4 * 32 * 4];   // W1: K=64  -> KSP=4   (8192 floats)
__device__ float g_W2p[16 * 8 * 32 * 4];   // W2: K=128 -> KSP=8   (16384 floats)

// ---------------- helpers ----------------
__device__ __forceinline__ unsigned f2tf32(float x) {
    unsigned u;
    asm("cvt.rna.tf32.f32 %0, %1;" : "=r"(u) : "f"(x));
    return u;
}
__device__ __forceinline__ float tf32f(float x) { return __uint_as_float(f2tf32(x)); }

// lane-slot permutation within a 32-lane packed group (bank spreading)
__device__ __forceinline__ int slot_of(int g, int q) { return g * 4 + ((q + (g >> 1)) & 3); }
__device__ __forceinline__ void inv_slot(int j, int& g, int& q) {
    g = j >> 2;
    q = ((j & 3) + 4 - ((g >> 1) & 3)) & 3;
}

__device__ __forceinline__ void mma_tf32(float c[4],
                                         unsigned a0, unsigned a1, unsigned a2, unsigned a3,
                                         unsigned b0, unsigned b1) {
    asm volatile(
        "mma.sync.aligned.m16n8k8.row.col.f32.tf32.tf32.f32 "
        "{%0,%1,%2,%3}, {%4,%5,%6,%7}, {%8,%9}, {%0,%1,%2,%3};"
        : "+f"(c[0]), "+f"(c[1]), "+f"(c[2]), "+f"(c[3])
        : "r"(a0), "r"(a1), "r"(a2), "r"(a3), "r"(b0), "r"(b1));
}

// ---------------- setup kernel: pack W1/W2 into fragment layout (once) --------------
__global__ void pack_weights(const float* __restrict__ W1, const float* __restrict__ W2) {
    const int idx = blockIdx.x * 256 + threadIdx.x;   // 6144 total
    if (idx < 2048) {                                  // W1p: nt(16) x ksp(4) x slot(32)
        const int js = idx & 31, ksp = (idx >> 5) & 3, nt = idx >> 7;
        int g, q; inv_slot(js, g, q);
        const int n = nt * 8 + g, k0 = ksp * 16 + q;
        float4 v;
        v.x = tf32f(W1[(k0     ) * D_DIM + n]);
        v.y = tf32f(W1[(k0 +  4) * D_DIM + n]);
        v.z = tf32f(W1[(k0 +  8) * D_DIM + n]);
        v.w = tf32f(W1[(k0 + 12) * D_DIM + n]);
        *reinterpret_cast<float4*>(&g_W1p[idx * 4]) = v;
    } else {                                           // W2p: nt(16) x ksp(8) x slot(32)
        const int i2 = idx - 2048;
        const int js = i2 & 31, ksp = (i2 >> 5) & 7, nt = i2 >> 8;
        int g, q; inv_slot(js, g, q);
        const int n = nt * 8 + g, k0 = ksp * 16 + q;
        float4 v;
        v.x = tf32f(W2[(k0     ) * M_DIM + n]);
        v.y = tf32f(W2[(k0 +  4) * M_DIM + n]);
        v.z = tf32f(W2[(k0 +  8) * M_DIM + n]);
        v.w = tf32f(W2[(k0 + 12) * M_DIM + n]);
        *reinterpret_cast<float4*>(&g_W2p[i2 * 4]) = v;
    }
}

// ---------------- packed-fragment GEMM: warp computes 32x32 tile --------------------
// A packed: entry (rg, ks, slot) float4 = {A[16rg+g][8ks+q], A[16rg+g+8][8ks+q],
//                                          A[16rg+g][8ks+q+4], A[16rg+g+8][8ks+q+4]}
// KS = 2*KSP. acc[h][ntl][4]: h = 16-row half, ntl = 8-col tile within the 32 cols.
template<int KSP>
__device__ __forceinline__ void gemm_packed(const float* __restrict__ PA,
                                            const float* __restrict__ PB,
                                            int rg2, int cg, int slotl,
                                            float acc[2][4][4]) {
    #pragma unroll
    for (int ksp = 0; ksp < KSP; ksp++) {
        float4 b[4], aE[2], aO[2];
        #pragma unroll
        for (int ntl = 0; ntl < 4; ntl++)
            b[ntl] = *reinterpret_cast<const float4*>(
                &PB[(((4 * cg + ntl) * KSP + ksp) * 32 + slotl) * 4]);
        #pragma unroll
        for (int h = 0; h < 2; h++) {
            aE[h] = *reinterpret_cast<const float4*>(
                &PA[(((2 * rg2 + h) * (2 * KSP) + 2 * ksp    ) * 32 + slotl) * 4]);
            aO[h] = *reinterpret_cast<const float4*>(
                &PA[(((2 * rg2 + h) * (2 * KSP) + 2 * ksp + 1) * 32 + slotl) * 4]);
        }
        #pragma unroll
        for (int h = 0; h < 2; h++)
            #pragma unroll
            for (int ntl = 0; ntl < 4; ntl++) {
                mma_tf32(acc[h][ntl],
                         __float_as_uint(aE[h].x), __float_as_uint(aE[h].y),
                         __float_as_uint(aE[h].z), __float_as_uint(aE[h].w),
                         __float_as_uint(b[ntl].x), __float_as_uint(b[ntl].y));
                mma_tf32(acc[h][ntl],
                         __float_as_uint(aO[h].x), __float_as_uint(aO[h].y),
                         __float_as_uint(aO[h].z), __float_as_uint(aO[h].w),
                         __float_as_uint(b[ntl].z), __float_as_uint(b[ntl].w));
            }
    }
}

__device__ __forceinline__ void zero_acc(float acc[2][4][4]) {
    #pragma unroll
    for (int h = 0; h < 2; h++)
        #pragma unroll
        for (int n = 0; n < 4; n++)
            #pragma unroll
            for (int r = 0; r < 4; r++) acc[h][n][r] = 0.0f;
}

// ---------------- SMEM layout (float offsets) ----------------
// region1 [0,16384):     Xp(8192) + W1p(8192)   UNION  Mainp(16384)
// region2 [16384,32768):  Hp(16384)
// region3 [32768,49152):  W2p(16384)  UNION  Sp(16384)
// biases  [49152,49408)
#define XP     0
#define W1P    8192
#define MAINP  0
#define HP     16384
#define W2P    32768
#define SP     32768
#define B1O    49152
#define B2O    49280
#define SMEM_FLOATS 49408
#define SMEM_BYTES  (SMEM_FLOATS * 4)   // 197632

__global__ __launch_bounds__(NTHREADS, 1)
void slam_fused_kernel(const float* __restrict__ x_main_last,
                       const float* __restrict__ x_aux,
                       const float* __restrict__ b1,
                       const float* __restrict__ b2,
                       float* __restrict__ out) {
    extern __shared__ float sm[];
    const int t    = blockIdx.x;
    const int tid  = threadIdx.x;
    const int warp = tid >> 5;
    const int lane = tid & 31;
    const int g    = lane >> 2;
    const int q    = lane & 3;
    const int rg2  = warp >> 2;   // 0..3: rows 32*rg2
    const int cg   = warp & 3;    // 0..3: cols 32*cg
    const int slotl = slot_of(g, q);

    // ---------- Phase 0: stage Xp (packed-A gather), copy W1p/W2p, biases ----------
    {
        const float* xp = x_aux + (size_t)t * A_DIM;
        #pragma unroll
        for (int it = 0; it < 4; it++) {
            const int idx = tid + it * NTHREADS;            // 2048 entries
            const int js = idx & 31, ks = (idx >> 5) & 7, rg = idx >> 8;
            int gg, qq; inv_slot(js, gg, qq);
            const int r0 = rg * 16 + gg, c0 = ks * 8 + qq;
            const size_t rs = (size_t)(T_DIM * A_DIM);
            float4 v;
            v.x = tf32f(xp[(size_t)(r0    ) * rs + c0    ]);
            v.y = tf32f(xp[(size_t)(r0 + 8) * rs + c0    ]);
            v.z = tf32f(xp[(size_t)(r0    ) * rs + c0 + 4]);
            v.w = tf32f(xp[(size_t)(r0 + 8) * rs + c0 + 4]);
            *reinterpret_cast<float4*>(&sm[XP + idx * 4]) = v;
        }
        #pragma unroll
        for (int it = 0; it < 4; it++) {                    // W1p copy: 2048 float4
            const int i = tid + it * NTHREADS;
            reinterpret_cast<float4*>(&sm[W1P])[i] =
                reinterpret_cast<const float4*>(g_W1p)[i];
        }
        #pragma unroll
        for (int it = 0; it < 8; it++) {                    // W2p copy: 4096 float4
            const int i = tid + it * NTHREADS;
            reinterpret_cast<float4*>(&sm[W2P])[i] =
                reinterpret_cast<const float4*>(g_W2p)[i];
        }
        if (tid < 128) {
            sm[B1O + tid] = b1[tid];
            sm[B2O + tid] = b2[tid];
        }
    }
    __syncthreads();

    float acc[2][4][4];
    const int hi  = (q >= 2) ? 2 : 0;       // e-offset from col bit2
    const int qc0 = (2 * q) & 3;            // consumer q for even col

    // ---------- GEMM1: H = relu(X @ W1 + b1) ----------
    zero_acc(acc);
    gemm_packed<4>(&sm[XP], &sm[W1P], rg2, cg, slotl, acc);

    // epilogue1 -> Hp (packed-A for GEMM2, KS=16)
    #pragma unroll
    for (int h = 0; h < 2; h++) {
        const int rg = 2 * rg2 + h;
        #pragma unroll
        for (int ntl = 0; ntl < 4; ntl++) {
            const int ks = 4 * cg + ntl;
            const int d0 = 32 * cg + 8 * ntl + 2 * q;
            const float bb0 = sm[B1O + d0], bb1 = sm[B1O + d0 + 1];
            const int base = (rg * 16 + ks) * 128;
            const int s0 = slot_of(g, qc0), s1 = slot_of(g, qc0 + 1);
            float2 w0, w1;
            w0.x = tf32f(fmaxf(acc[h][ntl][0] + bb0, 0.0f));   // (m0,d0) e=hi
            w0.y = tf32f(fmaxf(acc[h][ntl][2] + bb0, 0.0f));   // (m1,d0) e=hi+1
            w1.x = tf32f(fmaxf(acc[h][ntl][1] + bb1, 0.0f));   // (m0,d1)
            w1.y = tf32f(fmaxf(acc[h][ntl][3] + bb1, 0.0f));   // (m1,d1)
            *reinterpret_cast<float2*>(&sm[HP + base + s0 * 4 + hi]) = w0;
            *reinterpret_cast<float2*>(&sm[HP + base + s1 * 4 + hi]) = w1;
        }
    }
    __syncthreads();   // Hp complete; GEMM1 reads of region1 done

    // ---------- stage Mainp (packed-A for GEMM3, overwrites Xp/W1p) ----------
    {
        const float* mp = x_main_last + (size_t)t * (M_DIM * M_DIM);
        #pragma unroll
        for (int it = 0; it < 8; it++) {
            const int idx = tid + it * NTHREADS;            // 4096 entries
            const int js = idx & 31, ks = (idx >> 5) & 15, rg = idx >> 9;
            int gg, qq; inv_slot(js, gg, qq);
            const int r0 = rg * 16 + gg, c0 = ks * 8 + qq;
            float4 v;
            v.x = tf32f(mp[(r0    ) * M_DIM + c0    ]);
            v.y = tf32f(mp[(r0 + 8) * M_DIM + c0    ]);
            v.z = tf32f(mp[(r0    ) * M_DIM + c0 + 4]);
            v.w = tf32f(mp[(r0 + 8) * M_DIM + c0 + 4]);
            *reinterpret_cast<float4*>(&sm[MAINP + idx * 4]) = v;
        }
    }
    __syncthreads();

    // ---------- GEMM2: S = H @ W2 + b2 ----------
    zero_acc(acc);
    gemm_packed<8>(&sm[HP], &sm[W2P], rg2, cg, slotl, acc);
    __syncthreads();   // all W2p reads done before Sp overwrite

    // epilogue2 -> Sp (packed-B for GEMM3, KSP=8; k-dim = j = GEMM2 output row)
    #pragma unroll
    for (int h = 0; h < 2; h++) {
        const int ksp = 2 * rg2 + h;      // j>>4
        const int e0  = g >> 2;           // (j0>>2)&3
        #pragma unroll
        for (int ntl = 0; ntl < 4; ntl++) {
            const int nt = 4 * cg + ntl;
            const int n0 = 32 * cg + 8 * ntl + 2 * q;
            const float bb0 = sm[B2O + n0], bb1 = sm[B2O + n0 + 1];
            const int base = (nt * 8 + ksp) * 128;
            const int s0 = slot_of(2 * q,     g & 3);
            const int s1 = slot_of(2 * q + 1, g & 3);
            sm[SP + base + s0 * 4 + e0    ] = tf32f(acc[h][ntl][0] + bb0);  // (j0,n0)
            sm[SP + base + s1 * 4 + e0    ] = tf32f(acc[h][ntl][1] + bb1);  // (j0,n1)
            sm[SP + base + s0 * 4 + e0 + 2] = tf32f(acc[h][ntl][2] + bb0);  // (j1,n0)
            sm[SP + base + s1 * 4 + e0 + 2] = tf32f(acc[h][ntl][3] + bb1);  // (j1,n1)
        }
    }
    __syncthreads();

    // ---------- GEMM3: out_t = Main_t @ S ----------
    zero_acc(acc);
    gemm_packed<8>(&sm[MAINP], &sm[SP], rg2, cg, slotl, acc);

    // epilogue3 -> gmem
    float* op = out + (size_t)t * (M_DIM * M_DIM);
    #pragma unroll
    for (int h = 0; h < 2; h++) {
        const int i0 = 32 * rg2 + 16 * h + g;
        #pragma unroll
        for (int ntl = 0; ntl < 4; ntl++) {
            const int c0 = 32 * cg + 8 * ntl + 2 * q;
            float2 v0 = make_float2(acc[h][ntl][0], acc[h][ntl][1]);
            float2 v1 = make_float2(acc[h][ntl][2], acc[h][ntl][3]);
            *reinterpret_cast<float2*>(op + (size_t)(i0    ) * M_DIM + c0) = v0;
            *reinterpret_cast<float2*>(op + (size_t)(i0 + 8) * M_DIM + c0) = v1;
        }
    }
}

extern "C" void kernel_launch(void* const* d_in, const int* in_sizes, int n_in,
                              void* d_out, int out_size) {
    const float* x_main = (const float*)d_in[0];
    const float* x_aux  = (const float*)d_in[1];
    const float* W1     = (const float*)d_in[2];
    const float* b1     = (const float*)d_in[3];
    const float* W2     = (const float*)d_in[4];
    const float* b2     = (const float*)d_in[5];
    float* out = (float*)d_out;

    // last batch of x_main: x_main[N-1, :, 0, :, :]
    const size_t slice = (size_t)T_DIM * M_DIM * M_DIM;
    const float* x_main_last = x_main + ((size_t)in_sizes[0] - slice);

    cudaFuncSetAttribute(slam_fused_kernel,
                         cudaFuncAttributeMaxDynamicSharedMemorySize, SMEM_BYTES);

    pack_weights<<<24, 256>>>(W1, W2);
    slam_fused_kernel<<<T_DIM, NTHREADS, SMEM_BYTES>>>(x_main_last, x_aux, b1, b2, out);
}

// round 9
// speedup vs baseline: 1.9425x; 1.0188x over previous
#include <cuda_runtime.h>
#include <cstdint>
#include <cstddef>

// Problem constants
#define T_DIM 1024
#define M_DIM 128
#define A_DIM 64
#define D_DIM 128
#define NTHREADS 256

// ---------------- packed weight scratch (global, filled by setup kernel) -------------
// B-operand packed layout: entry (nt, ksp, slot) holds float4
//   e0 = B[16*ksp + q    ][8*nt + g]
//   e1 = B[16*ksp + q + 4][8*nt + g]
//   e2 = B[16*ksp + q + 8][8*nt + g]
//   e3 = B[16*ksp + q +12][8*nt + g]
// for consumer lane (g,q) stored at slot = g*4 + ((q + (g>>1)) & 3).
__device__ float g_W1p[16 * 4 * 32 * 4];   // W1: K=64  -> KSP=4   (8192 floats)
__device__ float g_W2p[16 * 8 * 32 * 4];   // W2: K=128 -> KSP=8   (16384 floats)

// ---------------- helpers ----------------
__device__ __forceinline__ unsigned f2tf32(float x) {
    unsigned u;
    asm("cvt.rna.tf32.f32 %0, %1;" : "=r"(u) : "f"(x));
    return u;
}
__device__ __forceinline__ float tf32f(float x) { return __uint_as_float(f2tf32(x)); }

// lane-slot permutation within a 32-lane packed group (bank spreading)
__device__ __forceinline__ int slot_of(int g, int q) { return g * 4 + ((q + (g >> 1)) & 3); }
__device__ __forceinline__ void inv_slot(int j, int& g, int& q) {
    g = j >> 2;
    q = ((j & 3) + 4 - ((g >> 1) & 3)) & 3;
}

__device__ __forceinline__ void mma_tf32(float c[4],
                                         unsigned a0, unsigned a1, unsigned a2, unsigned a3,
                                         unsigned b0, unsigned b1) {
    asm volatile(
        "mma.sync.aligned.m16n8k8.row.col.f32.tf32.tf32.f32 "
        "{%0,%1,%2,%3}, {%4,%5,%6,%7}, {%8,%9}, {%0,%1,%2,%3};"
        : "+f"(c[0]), "+f"(c[1]), "+f"(c[2]), "+f"(c[3])
        : "r"(a0), "r"(a1), "r"(a2), "r"(a3), "r"(b0), "r"(b1));
}

// ---------------- setup kernel: pack W1/W2 into fragment layout (once) --------------
__global__ void pack_weights(const float* __restrict__ W1, const float* __restrict__ W2) {
    const int idx = blockIdx.x * 256 + threadIdx.x;   // 6144 total
    if (idx < 2048) {                                  // W1p: nt(16) x ksp(4) x slot(32)
        const int js = idx & 31, ksp = (idx >> 5) & 3, nt = idx >> 7;
        int g, q; inv_slot(js, g, q);
        const int n = nt * 8 + g, k0 = ksp * 16 + q;
        float4 v;
        v.x = tf32f(W1[(k0     ) * D_DIM + n]);
        v.y = tf32f(W1[(k0 +  4) * D_DIM + n]);
        v.z = tf32f(W1[(k0 +  8) * D_DIM + n]);
        v.w = tf32f(W1[(k0 + 12) * D_DIM + n]);
        *reinterpret_cast<float4*>(&g_W1p[idx * 4]) = v;
    } else {                                           // W2p: nt(16) x ksp(8) x slot(32)
        const int i2 = idx - 2048;
        const int js = i2 & 31, ksp = (i2 >> 5) & 7, nt = i2 >> 8;
        int g, q; inv_slot(js, g, q);
        const int n = nt * 8 + g, k0 = ksp * 16 + q;
        float4 v;
        v.x = tf32f(W2[(k0     ) * M_DIM + n]);
        v.y = tf32f(W2[(k0 +  4) * M_DIM + n]);
        v.z = tf32f(W2[(k0 +  8) * M_DIM + n]);
        v.w = tf32f(W2[(k0 + 12) * M_DIM + n]);
        *reinterpret_cast<float4*>(&g_W2p[i2 * 4]) = v;
    }
}

// ---------------- packed-fragment GEMM: warp computes 64x32 tile --------------------
// A packed (smem): entry (rg, ks, slot) float4 = {A[16rg+g][8ks+q], A[16rg+g+8][8ks+q],
//                                                 A[16rg+g][8ks+q+4], A[16rg+g+8][8ks+q+4]}
// B packed (smem or global): entry (nt, ksp, slot) as documented above.
// Warp owns rows [64*rg2, 64*rg2+64), cols [32*cg, 32*cg+32).
// acc[rgl][ntl][4]: rgl = 16-row subgroup (0..3), ntl = 8-col tile (0..3).
template<int KSP>
__device__ __forceinline__ void gemm64(const float* __restrict__ PA,
                                       const float* __restrict__ PB,
                                       int rg2, int cg, int slotl,
                                       float acc[4][4][4]) {
    #pragma unroll
    for (int ksp = 0; ksp < KSP; ksp++) {
        float4 b[4], aE[4], aO[4];
        #pragma unroll
        for (int ntl = 0; ntl < 4; ntl++)
            b[ntl] = *reinterpret_cast<const float4*>(
                &PB[(((4 * cg + ntl) * KSP + ksp) * 32 + slotl) * 4]);
        #pragma unroll
        for (int rgl = 0; rgl < 4; rgl++) {
            const int rg = 4 * rg2 + rgl;
            aE[rgl] = *reinterpret_cast<const float4*>(
                &PA[((rg * (2 * KSP) + 2 * ksp    ) * 32 + slotl) * 4]);
            aO[rgl] = *reinterpret_cast<const float4*>(
                &PA[((rg * (2 * KSP) + 2 * ksp + 1) * 32 + slotl) * 4]);
        }
        #pragma unroll
        for (int rgl = 0; rgl < 4; rgl++)
            #pragma unroll
            for (int ntl = 0; ntl < 4; ntl++) {
                mma_tf32(acc[rgl][ntl],
                         __float_as_uint(aE[rgl].x), __float_as_uint(aE[rgl].y),
                         __float_as_uint(aE[rgl].z), __float_as_uint(aE[rgl].w),
                         __float_as_uint(b[ntl].x), __float_as_uint(b[ntl].y));
                mma_tf32(acc[rgl][ntl],
                         __float_as_uint(aO[rgl].x), __float_as_uint(aO[rgl].y),
                         __float_as_uint(aO[rgl].z), __float_as_uint(aO[rgl].w),
                         __float_as_uint(b[ntl].z), __float_as_uint(b[ntl].w));
            }
    }
}

__device__ __forceinline__ void zero_acc(float acc[4][4][4]) {
    #pragma unroll
    for (int a = 0; a < 4; a++)
        #pragma unroll
        for (int n = 0; n < 4; n++)
            #pragma unroll
            for (int r = 0; r < 4; r++) acc[a][n][r] = 0.0f;
}

// ---------------- SMEM layout (float offsets) ----------------
// region1 [0,16384):     Xp(8192) + pad   UNION  Mainp(16384)
// region2 [16384,32768): Hp(16384)        UNION  Sp(16384)
// biases  [32768,33024)
#define XP     0
#define MAINP  0
#define HP     16384
#define SP     16384
#define B1O    32768
#define B2O    32896
#define SMEM_FLOATS 33024
#define SMEM_BYTES  (SMEM_FLOATS * 4)   // 132096

__global__ __launch_bounds__(NTHREADS, 1)
void slam_fused_kernel(const float* __restrict__ x_main_last,
                       const float* __restrict__ x_aux,
                       const float* __restrict__ b1,
                       const float* __restrict__ b2,
                       float* __restrict__ out) {
    extern __shared__ float sm[];
    const int t    = blockIdx.x;
    const int tid  = threadIdx.x;
    const int warp = tid >> 5;
    const int lane = tid & 31;
    const int g    = lane >> 2;
    const int q    = lane & 3;
    const int rg2  = warp >> 2;   // 0..1: rows 64*rg2
    const int cg   = warp & 3;    // 0..3: cols 32*cg
    const int slotl = slot_of(g, q);

    // ---------- Phase 0: stage Xp (packed-A gather), biases ----------
    {
        const float* xp = x_aux + (size_t)t * A_DIM;
        #pragma unroll
        for (int it = 0; it < 8; it++) {
            const int idx = tid + it * NTHREADS;            // 2048 entries
            const int js = idx & 31, ks = (idx >> 5) & 7, rg = idx >> 8;
            int gg, qq; inv_slot(js, gg, qq);
            const int r0 = rg * 16 + gg, c0 = ks * 8 + qq;
            const size_t rs = (size_t)(T_DIM * A_DIM);
            float4 v;
            v.x = tf32f(xp[(size_t)(r0    ) * rs + c0    ]);
            v.y = tf32f(xp[(size_t)(r0 + 8) * rs + c0    ]);
            v.z = tf32f(xp[(size_t)(r0    ) * rs + c0 + 4]);
            v.w = tf32f(xp[(size_t)(r0 + 8) * rs + c0 + 4]);
            *reinterpret_cast<float4*>(&sm[XP + idx * 4]) = v;
        }
        if (tid < 128) {
            sm[B1O + tid] = b1[tid];
            sm[B2O + tid] = b2[tid];
        }
    }
    __syncthreads();

    float acc[4][4][4];
    const int hi  = (q >= 2) ? 2 : 0;       // e-offset from col bit2
    const int qc0 = (2 * q) & 3;            // consumer q for even col

    // ---------- GEMM1: H = relu(X @ W1 + b1)   (B from global, L1-cached) ----------
    zero_acc(acc);
    gemm64<4>(&sm[XP], g_W1p, rg2, cg, slotl, acc);
    __syncthreads();   // all GEMM1 reads of region1 done (Mainp overwrite below)

    // epilogue1 -> Hp (packed-A for GEMM2, KS=16)
    #pragma unroll
    for (int rgl = 0; rgl < 4; rgl++) {
        const int rg = 4 * rg2 + rgl;
        #pragma unroll
        for (int ntl = 0; ntl < 4; ntl++) {
            const int ks = 4 * cg + ntl;
            const int d0 = 32 * cg + 8 * ntl + 2 * q;
            const float bb0 = sm[B1O + d0], bb1 = sm[B1O + d0 + 1];
            const int base = (rg * 16 + ks) * 128;
            const int s0 = slot_of(g, qc0), s1 = slot_of(g, qc0 + 1);
            float2 w0, w1;
            w0.x = tf32f(fmaxf(acc[rgl][ntl][0] + bb0, 0.0f));   // (m0,d0)
            w0.y = tf32f(fmaxf(acc[rgl][ntl][2] + bb0, 0.0f));   // (m1,d0)
            w1.x = tf32f(fmaxf(acc[rgl][ntl][1] + bb1, 0.0f));   // (m0,d1)
            w1.y = tf32f(fmaxf(acc[rgl][ntl][3] + bb1, 0.0f));   // (m1,d1)
            *reinterpret_cast<float2*>(&sm[HP + base + s0 * 4 + hi]) = w0;
            *reinterpret_cast<float2*>(&sm[HP + base + s1 * 4 + hi]) = w1;
        }
    }

    // ---------- stage Mainp (packed-A for GEMM3, overwrites Xp) ----------
    {
        const float* mp = x_main_last + (size_t)t * (M_DIM * M_DIM);
        #pragma unroll
        for (int it = 0; it < 16; it++) {
            const int idx = tid + it * NTHREADS;            // 4096 entries
            const int js = idx & 31, ks = (idx >> 5) & 15, rg = idx >> 9;
            int gg, qq; inv_slot(js, gg, qq);
            const int r0 = rg * 16 + gg, c0 = ks * 8 + qq;
            float4 v;
            v.x = tf32f(mp[(r0    ) * M_DIM + c0    ]);
            v.y = tf32f(mp[(r0 + 8) * M_DIM + c0    ]);
            v.z = tf32f(mp[(r0    ) * M_DIM + c0 + 4]);
            v.w = tf32f(mp[(r0 + 8) * M_DIM + c0 + 4]);
            *reinterpret_cast<float4*>(&sm[MAINP + idx * 4]) = v;
        }
    }
    __syncthreads();

    // ---------- GEMM2: S = H @ W2 + b2   (B from global, L1-cached) ----------
    zero_acc(acc);
    gemm64<8>(&sm[HP], g_W2p, rg2, cg, slotl, acc);
    __syncthreads();   // all Hp reads done before Sp overwrite

    // epilogue2 -> Sp (packed-B for GEMM3, KSP=8; k-dim = j = GEMM2 output row)
    #pragma unroll
    for (int rgl = 0; rgl < 4; rgl++) {
        const int ksp = 4 * rg2 + rgl;    // j>>4
        const int e0  = g >> 2;           // (j0>>2)&3 ... element index for row j0
        #pragma unroll
        for (int ntl = 0; ntl < 4; ntl++) {
            const int nt = 4 * cg + ntl;
            const int n0 = 32 * cg + 8 * ntl + 2 * q;
            const float bb0 = sm[B2O + n0], bb1 = sm[B2O + n0 + 1];
            const int base = (nt * 8 + ksp) * 128;
            const int s0 = slot_of(2 * q,     g & 3);
            const int s1 = slot_of(2 * q + 1, g & 3);
            sm[SP + base + s0 * 4 + e0    ] = tf32f(acc[rgl][ntl][0] + bb0);  // (j0,n0)
            sm[SP + base + s1 * 4 + e0    ] = tf32f(acc[rgl][ntl][1] + bb1);  // (j0,n1)
            sm[SP + base + s0 * 4 + e0 + 2] = tf32f(acc[rgl][ntl][2] + bb0);  // (j1,n0)
            sm[SP + base + s1 * 4 + e0 + 2] = tf32f(acc[rgl][ntl][3] + bb1);  // (j1,n1)
        }
    }
    __syncthreads();

    // ---------- GEMM3: out_t = Main_t @ S ----------
    zero_acc(acc);
    gemm64<8>(&sm[MAINP], &sm[SP], rg2, cg, slotl, acc);

    // epilogue3 -> gmem
    float* op = out + (size_t)t * (M_DIM * M_DIM);
    #pragma unroll
    for (int rgl = 0; rgl < 4; rgl++) {
        const int i0 = 64 * rg2 + 16 * rgl + g;
        #pragma unroll
        for (int ntl = 0; ntl < 4; ntl++) {
            const int c0 = 32 * cg + 8 * ntl + 2 * q;
            float2 v0 = make_float2(acc[rgl][ntl][0], acc[rgl][ntl][1]);
            float2 v1 = make_float2(acc[rgl][ntl][2], acc[rgl][ntl][3]);
            *reinterpret_cast<float2*>(op + (size_t)(i0    ) * M_DIM + c0) = v0;
            *reinterpret_cast<float2*>(op + (size_t)(i0 + 8) * M_DIM + c0) = v1;
        }
    }
}

extern "C" void kernel_launch(void* const* d_in, const int* in_sizes, int n_in,
                              void* d_out, int out_size) {
    const float* x_main = (const float*)d_in[0];
    const float* x_aux  = (const float*)d_in[1];
    const float* W1     = (const float*)d_in[2];
    const float* b1     = (const float*)d_in[3];
    const float* W2     = (const float*)d_in[4];
    const float* b2     = (const float*)d_in[5];
    float* out = (float*)d_out;

    // last batch of x_main: x_main[N-1, :, 0, :, :]
    const size_t slice = (size_t)T_DIM * M_DIM * M_DIM;
    const float* x_main_last = x_main + ((size_t)in_sizes[0] - slice);

    cudaFuncSetAttribute(slam_fused_kernel,
                         cudaFuncAttributeMaxDynamicSharedMemorySize, SMEM_BYTES);

    pack_weights<<<24, 256>>>(W1, W2);
    slam_fused_kernel<<<T_DIM, NTHREADS, SMEM_BYTES>>>(x_main_last, x_aux, b1, b2, out);
}